// round 14
// baseline (speedup 1.0000x reference)
#include <cuda_runtime.h>
#include <math.h>

#define MAXK   5
#define CDIM   512
#define HWDIM  32768
#define TB     8
#define NTHR   512
#define NTILES (HWDIM / TB)                 // 4096
#define SMEM_BYTES (MAXK * CDIM * TB * 4)   // 81920 B -> 2 CTAs/SM

__device__ __forceinline__ void cp_async16(float* smem_dst, const float* gsrc) {
    unsigned int saddr = (unsigned int)__cvta_generic_to_shared(smem_dst);
    asm volatile("cp.async.cg.shared.global [%0], [%1], 16;\n"
                 :: "r"(saddr), "l"(gsrc));
}
#define CP_COMMIT()  asm volatile("cp.async.commit_group;\n" ::: "memory")
#define CP_WAIT(n)   asm volatile("cp.async.wait_group %0;\n" :: "n"(n) : "memory")

__global__ __launch_bounds__(NTHR, 2)
void attfusion_kernel(const float* __restrict__ x,
                      const int* __restrict__ record_len,
                      float* __restrict__ out) {
    extern __shared__ float s[];             // s[(k*CDIM + c)*TB + bl]
    __shared__ float part[16][TB][MAXK];
    __shared__ float wgt[TB][MAXK];

    const int t  = threadIdx.x;
    const int b0 = blockIdx.x * TB;
    int rl = *record_len;
    rl = rl < 0 ? 0 : (rl > MAXK ? MAXK : rl);

    const int c0 = t >> 1;                   // 0..255
    const int q  = (t & 1) << 2;             // 0 or 4

    if (rl == 0) {
        const float4 z = make_float4(0.f, 0.f, 0.f, 0.f);
        *(float4*)(out + (size_t)c0 * HWDIM + b0 + q)         = z;
        *(float4*)(out + (size_t)(c0 + 256) * HWDIM + b0 + q) = z;
        return;
    }

    // ---------------- Issue loads: one cp.async group per k (FIFO completion)
    #pragma unroll
    for (int k = 0; k < MAXK; ++k) {
        if (k < rl) {
            const float* xk = x + (size_t)k * CDIM * HWDIM + b0 + q;
            cp_async16(s + (k * CDIM + c0)       * TB + q, xk + (size_t)c0 * HWDIM);
            cp_async16(s + (k * CDIM + c0 + 256) * TB + q, xk + (size_t)(c0 + 256) * HWDIM);
        }
        CP_COMMIT();                         // commit even if empty: static group count
    }

    // ---------------- Pipelined dot: consume slice k as it lands (all 16 warps)
    const int w    = t >> 5;                 // 0..15
    const int lane = t & 31;
    const int bl   = lane & 7;               // spatial position
    const int cseg = lane >> 3;              // 0..3
    const int cbase = w * 32 + cseg;         // c = cbase + 4*i, i<8

    float t0r[8];
    float acc[MAXK];

    // stage k = 0
    CP_WAIT(MAXK - 1);
    __syncthreads();
    {
        float a = 0.0f;
        #pragma unroll
        for (int i = 0; i < 8; ++i) {
            t0r[i] = s[(cbase + 4 * i) * TB + bl];
            a += t0r[i] * t0r[i];
        }
        acc[0] = a;
    }
    // stages k = 1..4
    #pragma unroll
    for (int k = 1; k < MAXK; ++k) {
        if (k < rl) {
            if (k == 1) CP_WAIT(MAXK - 2);
            if (k == 2) CP_WAIT(MAXK - 3);
            if (k == 3) CP_WAIT(MAXK - 4);
            if (k == 4) CP_WAIT(0);
            __syncthreads();
            float a = 0.0f;
            const float* sk = s + k * CDIM * TB;
            #pragma unroll
            for (int i = 0; i < 8; ++i)
                a += t0r[i] * sk[(cbase + 4 * i) * TB + bl];
            acc[k] = a;
        } else {
            acc[k] = 0.0f;
        }
    }
    CP_WAIT(0);                               // all slices resident (for output phase)

    // reduce across cseg (lanes differing in bits 3,4 share bl)
    #pragma unroll
    for (int k = 0; k < MAXK; ++k) {
        if (k < rl) {
            float v = acc[k];
            v += __shfl_xor_sync(0xffffffffu, v, 8);
            v += __shfl_xor_sync(0xffffffffu, v, 16);
            acc[k] = v;
        }
    }
    if (lane < 8) {
        #pragma unroll
        for (int k = 0; k < MAXK; ++k)
            if (k < rl) part[w][lane][k] = acc[k];
    }
    __syncthreads();

    // ---------------- Softmax (threads 0..7, one per bl)
    if (t < TB) {
        const float scale = 0.044194173824159216f;   // 1/sqrt(512)
        float d[MAXK];
        #pragma unroll
        for (int k = 0; k < MAXK; ++k) {
            float sum = 0.0f;
            #pragma unroll
            for (int ww = 0; ww < 16; ++ww) sum += part[ww][t][k];
            d[k] = sum * scale;
        }
        float m = -INFINITY;
        #pragma unroll
        for (int k = 0; k < MAXK; ++k)
            if (k < rl) m = fmaxf(m, d[k]);
        float e[MAXK], esum = 0.0f;
        #pragma unroll
        for (int k = 0; k < MAXK; ++k) {
            e[k] = (k < rl) ? expf(d[k] - m) : 0.0f;
            esum += e[k];
        }
        float inv = 1.0f / esum;
        #pragma unroll
        for (int k = 0; k < MAXK; ++k) wgt[t][k] = e[k] * inv;
    }
    __syncthreads();

    // ---------------- Output phase: float4 over b-quads, all k from SMEM
    {
        const int qb = q;                     // b-quad base: 0 or 4
        float w4[MAXK][4];
        #pragma unroll
        for (int k = 0; k < MAXK; ++k)
            #pragma unroll
            for (int j = 0; j < 4; ++j)
                w4[k][j] = wgt[qb + j][k];

        #pragma unroll
        for (int slot = 0; slot < 2; ++slot) {
            int c = c0 + 256 * slot;
            float4 v = make_float4(0.f, 0.f, 0.f, 0.f);
            #pragma unroll
            for (int k = 0; k < MAXK; ++k) {
                if (k < rl) {
                    float4 tk = *(const float4*)(s + (k * CDIM + c) * TB + qb);
                    v.x += w4[k][0] * tk.x;
                    v.y += w4[k][1] * tk.y;
                    v.z += w4[k][2] * tk.z;
                    v.w += w4[k][3] * tk.w;
                }
            }
            *(float4*)(out + (size_t)c * HWDIM + b0 + qb) = v;
        }
    }
}

extern "C" void kernel_launch(void* const* d_in, const int* in_sizes, int n_in,
                              void* d_out, int out_size) {
    const float* x  = (const float*)d_in[0];
    const int* rl   = (const int*)d_in[1];
    float* out      = (float*)d_out;
    cudaFuncSetAttribute(attfusion_kernel,
                         cudaFuncAttributeMaxDynamicSharedMemorySize, SMEM_BYTES);
    attfusion_kernel<<<NTILES, NTHR, SMEM_BYTES>>>(x, rl, out);
}

// round 15
// speedup vs baseline: 1.0069x; 1.0069x over previous
#include <cuda_runtime.h>
#include <math.h>

#define MAXK   5
#define CDIM   512
#define HWDIM  32768
#define TB     8
#define NTHR   512
#define NTILES (HWDIM / TB)                 // 4096
#define SMEM_BYTES (MAXK * CDIM * TB * 4)   // 81920 B -> 2 CTAs/SM

__device__ __forceinline__ void cp_async16(float* smem_dst, const float* gsrc) {
    unsigned int saddr = (unsigned int)__cvta_generic_to_shared(smem_dst);
    asm volatile("cp.async.cg.shared.global [%0], [%1], 16;\n"
                 :: "r"(saddr), "l"(gsrc));
}
#define CP_COMMIT()  asm volatile("cp.async.commit_group;\n" ::: "memory")
#define CP_WAIT(n)   asm volatile("cp.async.wait_group %0;\n" :: "n"(n) : "memory")

__global__ __launch_bounds__(NTHR, 2)
void attfusion_kernel(const float* __restrict__ x,
                      const int* __restrict__ record_len,
                      float* __restrict__ out) {
    extern __shared__ float s[];             // s[(k*CDIM + c)*TB + bl]
    __shared__ float part[16][TB][MAXK];
    __shared__ float wgt[TB][MAXK];

    const int t  = threadIdx.x;
    const int b0 = blockIdx.x * TB;
    int rl = *record_len;
    rl = rl < 0 ? 0 : (rl > MAXK ? MAXK : rl);

    const int c0 = t >> 1;                   // 0..255
    const int q  = (t & 1) << 2;             // 0 or 4

    if (rl == 0) {
        const float4 z = make_float4(0.f, 0.f, 0.f, 0.f);
        *(float4*)(out + (size_t)c0 * HWDIM + b0 + q)         = z;
        *(float4*)(out + (size_t)(c0 + 256) * HWDIM + b0 + q) = z;
        return;
    }

    // ---------------- Issue loads: one cp.async group per k (FIFO completion)
    #pragma unroll
    for (int k = 0; k < MAXK; ++k) {
        if (k < rl) {
            const float* xk = x + (size_t)k * CDIM * HWDIM + b0 + q;
            cp_async16(s + (k * CDIM + c0)       * TB + q, xk + (size_t)c0 * HWDIM);
            cp_async16(s + (k * CDIM + c0 + 256) * TB + q, xk + (size_t)(c0 + 256) * HWDIM);
        }
        CP_COMMIT();                         // commit even if empty: static group count
    }

    // ---------------- Pipelined dot: consume slice k as it lands (all 16 warps)
    const int w    = t >> 5;                 // 0..15
    const int lane = t & 31;
    const int bl   = lane & 7;               // spatial position
    const int cseg = lane >> 3;              // 0..3
    const int cbase = w * 32 + cseg;         // c = cbase + 4*i, i<8

    float t0r[8];
    float acc[MAXK];

    // stage k = 0
    CP_WAIT(MAXK - 1);
    __syncthreads();
    {
        float a = 0.0f;
        #pragma unroll
        for (int i = 0; i < 8; ++i) {
            t0r[i] = s[(cbase + 4 * i) * TB + bl];
            a += t0r[i] * t0r[i];
        }
        acc[0] = a;
    }
    // stages k = 1..4
    #pragma unroll
    for (int k = 1; k < MAXK; ++k) {
        if (k < rl) {
            if (k == 1) CP_WAIT(MAXK - 2);
            if (k == 2) CP_WAIT(MAXK - 3);
            if (k == 3) CP_WAIT(MAXK - 4);
            if (k == 4) CP_WAIT(0);
            __syncthreads();
            float a = 0.0f;
            const float* sk = s + k * CDIM * TB;
            #pragma unroll
            for (int i = 0; i < 8; ++i)
                a += t0r[i] * sk[(cbase + 4 * i) * TB + bl];
            acc[k] = a;
        } else {
            acc[k] = 0.0f;
        }
    }
    CP_WAIT(0);                               // all slices resident (for output phase)

    // reduce across cseg (lanes differing in bits 3,4 share bl)
    #pragma unroll
    for (int k = 0; k < MAXK; ++k) {
        if (k < rl) {
            float v = acc[k];
            v += __shfl_xor_sync(0xffffffffu, v, 8);
            v += __shfl_xor_sync(0xffffffffu, v, 16);
            acc[k] = v;
        }
    }
    if (lane < 8) {
        #pragma unroll
        for (int k = 0; k < MAXK; ++k)
            if (k < rl) part[w][lane][k] = acc[k];
    }
    __syncthreads();

    // ---------------- Softmax (threads 0..7, one per bl)
    if (t < TB) {
        const float scale = 0.044194173824159216f;   // 1/sqrt(512)
        float d[MAXK];
        #pragma unroll
        for (int k = 0; k < MAXK; ++k) {
            float sum = 0.0f;
            #pragma unroll
            for (int ww = 0; ww < 16; ++ww) sum += part[ww][t][k];
            d[k] = sum * scale;
        }
        float m = -INFINITY;
        #pragma unroll
        for (int k = 0; k < MAXK; ++k)
            if (k < rl) m = fmaxf(m, d[k]);
        float e[MAXK], esum = 0.0f;
        #pragma unroll
        for (int k = 0; k < MAXK; ++k) {
            e[k] = (k < rl) ? expf(d[k] - m) : 0.0f;
            esum += e[k];
        }
        float inv = 1.0f / esum;
        #pragma unroll
        for (int k = 0; k < MAXK; ++k) wgt[t][k] = e[k] * inv;
    }
    __syncthreads();

    // ---------------- Output phase: float4 over b-quads, all k from SMEM
    {
        const int qb = q;                     // b-quad base: 0 or 4
        float w4[MAXK][4];
        #pragma unroll
        for (int k = 0; k < MAXK; ++k)
            #pragma unroll
            for (int j = 0; j < 4; ++j)
                w4[k][j] = wgt[qb + j][k];

        #pragma unroll
        for (int slot = 0; slot < 2; ++slot) {
            int c = c0 + 256 * slot;
            float4 v = make_float4(0.f, 0.f, 0.f, 0.f);
            #pragma unroll
            for (int k = 0; k < MAXK; ++k) {
                if (k < rl) {
                    float4 tk = *(const float4*)(s + (k * CDIM + c) * TB + qb);
                    v.x += w4[k][0] * tk.x;
                    v.y += w4[k][1] * tk.y;
                    v.z += w4[k][2] * tk.z;
                    v.w += w4[k][3] * tk.w;
                }
            }
            *(float4*)(out + (size_t)c * HWDIM + b0 + qb) = v;
        }
    }
}

extern "C" void kernel_launch(void* const* d_in, const int* in_sizes, int n_in,
                              void* d_out, int out_size) {
    const float* x  = (const float*)d_in[0];
    const int* rl   = (const int*)d_in[1];
    float* out      = (float*)d_out;
    cudaFuncSetAttribute(attfusion_kernel,
                         cudaFuncAttributeMaxDynamicSharedMemorySize, SMEM_BYTES);
    attfusion_kernel<<<NTILES, NTHR, SMEM_BYTES>>>(x, rl, out);
}